// round 12
// baseline (speedup 1.0000x reference)
#include <cuda_runtime.h>
#include <cuda_bf16.h>
#include <cuda_fp16.h>
#include <cstdint>

#define B_      8
#define Q_      2048
#define DIM_    256
#define NH      8
#define HD      32
#define DFF     1024
#define LEN_IN_ 13294
#define BQ      (B_*Q_)
#define MV      (B_*LEN_IN_)

// ---------------- scratch ----------------
__device__ float    g_qp[BQ*DIM_];
__device__ __half   g_valh[MV*DIM_];       // fp16 value (54 MB, L2-resident)
__device__ float    g_offattn[BQ*384];     // [off(256) | attn logits(128)]
__device__ float    g_attnout[BQ*DIM_];
__device__ float    g_x[BQ*DIM_];
__device__ float    g_y[BQ*DIM_];
__device__ float    g_ffn[BQ*DFF];
__device__ uint32_t g_wp[376832];          // packed bf16x2 weights (fragment layout)
__device__ float    g_bcat[384];           // concat bias [boff | battn]

// packed-weight word offsets
#define WP_WV    0
#define WP_PROJ  32768
#define WP_WOUT  81920
#define WP_W1    114688
#define WP_W2    245760

// ---------------- LayerNorm (+ optional additive term) ----------------
__global__ __launch_bounds__(256) void ln_kernel(
    const float* __restrict__ x, const float* __restrict__ g,
    const float* __restrict__ b, const float* __restrict__ addend,
    float* __restrict__ out)
{
    __shared__ float sbuf[8];
    const int row = blockIdx.x;
    const int t = threadIdx.x;
    const float v = x[(size_t)row*DIM_ + t];

    float s = v;
    #pragma unroll
    for (int o = 16; o; o >>= 1) s += __shfl_xor_sync(0xffffffffu, s, o);
    if ((t & 31) == 0) sbuf[t >> 5] = s;
    __syncthreads();
    float mean = 0.f;
    #pragma unroll
    for (int i = 0; i < 8; i++) mean += sbuf[i];
    mean *= (1.f/256.f);

    const float d = v - mean;
    float s2 = d*d;
    #pragma unroll
    for (int o = 16; o; o >>= 1) s2 += __shfl_xor_sync(0xffffffffu, s2, o);
    __syncthreads();
    if ((t & 31) == 0) sbuf[t >> 5] = s2;
    __syncthreads();
    float var = 0.f;
    #pragma unroll
    for (int i = 0; i < 8; i++) var += sbuf[i];
    var *= (1.f/256.f);

    float r = d * rsqrtf(var + 1e-5f) * g[t] + b[t];
    if (addend) r += addend[(size_t)row*DIM_ + t];
    out[(size_t)row*DIM_ + t] = r;
}

// ---------------- helpers ----------------
__device__ __forceinline__ uint32_t packbf(float lo, float hi) {
    uint32_t d;
    asm("cvt.rn.bf16x2.f32 %0, %1, %2;" : "=r"(d) : "f"(hi), "f"(lo));
    return d;
}

__device__ __forceinline__ void mma_bf16(float c[4], const uint32_t a[4],
                                         uint32_t b0, uint32_t b1) {
    asm("mma.sync.aligned.m16n8k16.row.col.f32.bf16.bf16.f32 "
        "{%0,%1,%2,%3}, {%4,%5,%6,%7}, {%8,%9}, {%0,%1,%2,%3};"
        : "+f"(c[0]), "+f"(c[1]), "+f"(c[2]), "+f"(c[3])
        : "r"(a[0]), "r"(a[1]), "r"(a[2]), "r"(a[3]), "r"(b0), "r"(b1));
}

// ---------------- single-launch weight pack (fragment-direct layout) ----------------
struct WPackArgs {
    const float *Wv, *Woff, *Wattn, *Wout, *W1, *W2, *boff, *battn;
};

__device__ __forceinline__ uint32_t frag_pack(const float* __restrict__ W,
                                              int N, int K32, int idx)
{
    const int blk  = idx >> 7;
    const int r    = idx & 127;
    const int lane = r >> 2;
    const int j    = r & 3;
    const int gid  = lane >> 2;
    const int tig  = lane & 3;
    const int n8   = blk / K32;
    const int t    = blk - n8 * K32;
    const int kp   = t*16 + tig + j*4;
    const int n    = n8*8 + gid;
    return packbf(W[(size_t)(2*kp)*N + n], W[(size_t)(2*kp+1)*N + n]);
}

__global__ __launch_bounds__(256) void wconv_all(WPackArgs a, uint32_t* __restrict__ out,
                                                 float* __restrict__ bcat)
{
    int idx = blockIdx.x * 256 + threadIdx.x;

    if (idx < 32768) { out[WP_WV + idx] = frag_pack(a.Wv, 256, 8, idx); return; }
    idx -= 32768;
    if (idx < 49152) {   // projcat K=256, N=384
        const int blk  = idx >> 7;
        const int r    = idx & 127;
        const int lane = r >> 2;
        const int j    = r & 3;
        const int gid  = lane >> 2;
        const int tig  = lane & 3;
        const int n8   = blk >> 3;
        const int t    = blk & 7;
        const int kp   = t*16 + tig + j*4;
        const int n    = n8*8 + gid;
        float lo, hi;
        if (n < 256) { lo = a.Woff[(size_t)(2*kp)*256 + n];      hi = a.Woff[(size_t)(2*kp+1)*256 + n]; }
        else         { lo = a.Wattn[(size_t)(2*kp)*128 + n-256]; hi = a.Wattn[(size_t)(2*kp+1)*128 + n-256]; }
        out[WP_PROJ + idx] = packbf(lo, hi);
        return;
    }
    idx -= 49152;
    if (idx < 32768) { out[WP_WOUT + idx] = frag_pack(a.Wout, 256, 8, idx); return; }
    idx -= 32768;
    if (idx < 131072) { out[WP_W1 + idx] = frag_pack(a.W1, 1024, 8, idx); return; }
    idx -= 131072;
    if (idx < 131072) { out[WP_W2 + idx] = frag_pack(a.W2, 256, 32, idx); return; }
    idx -= 131072;
    if (idx < 384) bcat[idx] = (idx < 256) ? a.boff[idx] : a.battn[idx - 256];
}

// ---------------- BF16 tensor-core GEMM, distance-2 A prefetch ----------------
// C = act(A @ W + bias) [+resid] [mask rows]; optional fp16 output.
// A fp32 [M,K]; Wp fragment layout. CTA: 128 threads, tile 64 x (WNT*32).
// A registers double-buffered with prefetch distance 2 (LDG A(t+2) in iter t),
// B fragments register double-buffered (distance 1, L2-hot weights).
#define A_STRB   80
#define A_STAGEB (64*A_STRB)

template<int WNT>
__global__ __launch_bounds__(128) void gemm_bf(
    const float* __restrict__ A, const uint32_t* __restrict__ Wp,
    const float* __restrict__ bias, const float* __restrict__ resid,
    const uint8_t* __restrict__ mask, void* __restrict__ Cv,
    int M, int N, int K, int relu, int outhalf)
{
    __shared__ char smem[2*A_STAGEB];

    const int tid   = threadIdx.x;
    const int warpN = tid >> 5;
    const int lane  = tid & 31;
    const int gid   = lane >> 2;
    const int tig   = lane & 3;
    const int row0  = blockIdx.y * 64;
    const int col0  = blockIdx.x * (WNT*32);
    const int K32   = K >> 5;
    const int nblk0 = (col0 >> 3) + warpN*WNT;

    const int a_row  = tid >> 1;
    const int a_half = tid & 1;
    const bool avalid = (row0 + a_row) < M;
    const float* aptr = A + (size_t)(row0 + a_row) * K + a_half*16;

    const int lrow   = (lane & 7) + (((lane >> 3) & 1) << 3);
    const int lkhalf = (lane >> 4) & 1;
    const uint32_t a_sbase = (uint32_t)__cvta_generic_to_shared(smem);

    float acc[4][WNT][4];
    #pragma unroll
    for (int i = 0; i < 4; i++)
        #pragma unroll
        for (int j = 0; j < WNT; j++)
            #pragma unroll
            for (int r = 0; r < 4; r++) acc[i][j][r] = 0.f;

    float4 ra[2][4];                      // A register ring, prefetch distance 2
    auto ldgA = [&](int slot, int t) {
        const int k0 = t << 5;
        #pragma unroll
        for (int i = 0; i < 4; i++)
            ra[slot][i] = avalid ? *(const float4*)(aptr + k0 + i*4)
                                 : make_float4(0.f,0.f,0.f,0.f);
    };
    auto stsA = [&](int slot, int p) {
        uint32_t w[8];
        #pragma unroll
        for (int i = 0; i < 4; i++) {
            w[i*2+0] = packbf(ra[slot][i].x, ra[slot][i].y);
            w[i*2+1] = packbf(ra[slot][i].z, ra[slot][i].w);
        }
        char* dst = smem + p*A_STAGEB + a_row*A_STRB + a_half*32;
        *(uint4*)(dst)      = make_uint4(w[0], w[1], w[2], w[3]);
        *(uint4*)(dst + 16) = make_uint4(w[4], w[5], w[6], w[7]);
    };

    uint4 bqb[2][WNT];
    auto ldgB = [&](int slot, int t) {
        #pragma unroll
        for (int nt = 0; nt < WNT; nt++)
            bqb[slot][nt] = *(const uint4*)(Wp
                + (((size_t)(nblk0 + nt)*K32 + t) << 7) + (lane << 2));
    };

    // ---- prologue: A(0), A(1), B(0); stage 0 filled ----
    ldgA(0, 0);
    ldgA(1, 1);
    ldgB(0, 0);
    stsA(0, 0);

    #pragma unroll 2
    for (int t = 0; t < K32; t++) {
        const int p = t & 1;
        __syncthreads();

        if (t + 2 < K32) ldgA(p, t + 2);          // ra[p] free: consumed by stsA in iter t-1
        if (t + 1 < K32) ldgB(p ^ 1, t + 1);

        // ---- all A fragments up front (8 LDSM), then MMA chain ----
        const uint32_t a_stage = a_sbase + (uint32_t)(p * A_STAGEB);
        uint32_t af[2][4][4];
        #pragma unroll
        for (int ks = 0; ks < 2; ks++)
            #pragma unroll
            for (int mt = 0; mt < 4; mt++) {
                const uint32_t addr = a_stage
                    + (uint32_t)((mt*16 + lrow)*A_STRB + ks*32 + lkhalf*16);
                asm volatile("ldmatrix.sync.aligned.m8n8.x4.shared.b16 {%0,%1,%2,%3}, [%4];"
                    : "=r"(af[ks][mt][0]), "=r"(af[ks][mt][1]),
                      "=r"(af[ks][mt][2]), "=r"(af[ks][mt][3]) : "r"(addr));
            }
        #pragma unroll
        for (int ks = 0; ks < 2; ks++)
            #pragma unroll
            for (int mt = 0; mt < 4; mt++)
                #pragma unroll
                for (int nt = 0; nt < WNT; nt++) {
                    if (ks == 0) mma_bf16(acc[mt][nt], af[0][mt], bqb[p][nt].x, bqb[p][nt].y);
                    else         mma_bf16(acc[mt][nt], af[1][mt], bqb[p][nt].z, bqb[p][nt].w);
                }

        if (t + 1 < K32) stsA(p ^ 1, p ^ 1);       // A(t+1) was loaded in iter t-1
    }

    // ---- epilogue ----
    #pragma unroll
    for (int mt = 0; mt < 4; mt++) {
        #pragma unroll
        for (int half = 0; half < 2; half++) {
            const int r = row0 + mt*16 + gid + half*8;
            if (r >= M) continue;
            const float mz = (mask && mask[r]) ? 0.f : 1.f;
            #pragma unroll
            for (int nt = 0; nt < WNT; nt++) {
                const int c = col0 + warpN*WNT*8 + nt*8 + 2*tig;
                float v0 = acc[mt][nt][half*2 + 0] + bias[c + 0];
                float v1 = acc[mt][nt][half*2 + 1] + bias[c + 1];
                if (relu) { v0 = fmaxf(v0, 0.f); v1 = fmaxf(v1, 0.f); }
                if (resid) {
                    const float* rp = resid + (size_t)r*N + c;
                    v0 += rp[0]; v1 += rp[1];
                }
                v0 *= mz; v1 *= mz;
                if (outhalf) {
                    __half2* hp = (__half2*)((__half*)Cv + (size_t)r*N + c);
                    *hp = __floats2half2_rn(v0, v1);
                } else {
                    *(float2*)((float*)Cv + (size_t)r*N + c) = make_float2(v0, v1);
                }
            }
        }
    }
}

// ---------------- fused loc + softmax + MS-deformable sampling (fp16 value) ----------------
__global__ __launch_bounds__(128) void sample_kernel(
    const __half* __restrict__ value, const float* __restrict__ offattn,
    const float* __restrict__ ref,
    float* __restrict__ out_loc, float* __restrict__ out)
{
    __shared__ float s_loc[256];
    __shared__ float s_attn[128];

    const int bq   = blockIdx.x;
    const int tid  = threadIdx.x;
    const int b    = bq >> 11;

    #pragma unroll
    for (int i = 0; i < 2; i++) {
        const int j = tid + i*128;
        const int c = j & 1;
        const int l = (j >> 3) & 3;
        const float nd[4] = {100.f, 50.f, 25.f, 13.f};
        const float v = ref[((size_t)bq*4 + l)*2 + c]
                      + offattn[(size_t)bq*384 + j] / nd[l];
        s_loc[j] = v;
        out_loc[(size_t)bq*256 + j] = v;
    }
    {
        const float logit = offattn[(size_t)bq*384 + 256 + tid];
        float m = logit;
        #pragma unroll
        for (int o = 8; o; o >>= 1) m = fmaxf(m, __shfl_xor_sync(0xffffffffu, m, o, 16));
        const float e = __expf(logit - m);
        float s = e;
        #pragma unroll
        for (int o = 8; o; o >>= 1) s += __shfl_xor_sync(0xffffffffu, s, o, 16);
        s_attn[tid] = e / s;
    }
    __syncthreads();

    const int warp = tid >> 5;
    const int lane = tid & 31;
    const int h    = warp*2 + (lane >> 4);
    const int cp   = lane & 15;

    const float* locp = s_loc  + h*32;
    const float* ap   = s_attn + h*16;

    constexpr int LH[4] = {100, 50, 25, 13};
    constexpr int LS[4] = {0, 10000, 12500, 13125};

    float a0 = 0.f, a1 = 0.f;
    #pragma unroll
    for (int l = 0; l < 4; l++) {
        const int Hh = LH[l], Ww = LH[l];
        const __half2* vb = (const __half2*)(value
            + ((size_t)b*LEN_IN_ + LS[l])*DIM_ + h*32) + cp;
        #pragma unroll
        for (int p = 0; p < 4; p++) {
            const float lx = locp[(l*4 + p)*2 + 0];
            const float ly = locp[(l*4 + p)*2 + 1];
            const float a  = ap[l*4 + p];
            const float x = lx * (float)Ww - 0.5f;
            const float y = ly * (float)Hh - 0.5f;
            const float x0f = floorf(x), y0f = floorf(y);
            const float wx = x - x0f, wy = y - y0f;
            const int x0 = (int)x0f, y0 = (int)y0f;
            const int x1 = x0 + 1,  y1 = y0 + 1;

            const float vx0 = (x0 >= 0 && x0 < Ww) ? 1.f : 0.f;
            const float vx1 = (x1 >= 0 && x1 < Ww) ? 1.f : 0.f;
            const float vy0 = (y0 >= 0 && y0 < Hh) ? 1.f : 0.f;
            const float vy1 = (y1 >= 0 && y1 < Hh) ? 1.f : 0.f;
            const int cx0 = min(max(x0, 0), Ww-1);
            const int cx1 = min(max(x1, 0), Ww-1);
            const int cy0 = min(max(y0, 0), Hh-1);
            const int cy1 = min(max(y1, 0), Hh-1);

            const float2 g00 = __half22float2(vb[(size_t)(cy0*Ww + cx0)*128]);
            const float2 g01 = __half22float2(vb[(size_t)(cy0*Ww + cx1)*128]);
            const float2 g10 = __half22float2(vb[(size_t)(cy1*Ww + cx0)*128]);
            const float2 g11 = __half22float2(vb[(size_t)(cy1*Ww + cx1)*128]);

            const float w00 = vx0*vy0*(1.f-wx)*(1.f-wy);
            const float w01 = vx1*vy0*wx*(1.f-wy);
            const float w10 = vx0*vy1*(1.f-wx)*wy;
            const float w11 = vx1*vy1*wx*wy;

            a0 += a * (g00.x*w00 + g01.x*w01 + g10.x*w10 + g11.x*w11);
            a1 += a * (g00.y*w00 + g01.y*w01 + g10.y*w10 + g11.y*w11);
        }
    }
    *(float2*)(out + (size_t)bq*256 + h*32 + cp*2) = make_float2(a0, a1);
}

// ---------------- launch ----------------
extern "C" void kernel_launch(void* const* d_in, const int* in_sizes, int n_in,
                              void* d_out, int out_size)
{
    const float*   input  = (const float*)d_in[0];
    const float*   pos    = (const float*)d_in[1];
    const float*   refp   = (const float*)d_in[2];
    const float*   source = (const float*)d_in[3];
    const uint8_t* mask   = (const uint8_t*)d_in[6];
    const float*   ln1_g  = (const float*)d_in[7];
    const float*   ln1_b  = (const float*)d_in[8];
    const float*   ln2_g  = (const float*)d_in[9];
    const float*   ln2_b  = (const float*)d_in[10];
    const float*   Wv     = (const float*)d_in[11];
    const float*   bv     = (const float*)d_in[12];
    const float*   Woff   = (const float*)d_in[13];
    const float*   boff   = (const float*)d_in[14];
    const float*   Wattn  = (const float*)d_in[15];
    const float*   battn  = (const float*)d_in[16];
    const float*   Wout   = (const float*)d_in[17];
    const float*   bout   = (const float*)d_in[18];
    const float*   W1     = (const float*)d_in[19];
    const float*   b1     = (const float*)d_in[20];
    const float*   W2     = (const float*)d_in[21];
    const float*   b2     = (const float*)d_in[22];

    float* out_x   = (float*)d_out;
    float* out_loc = (float*)d_out + (size_t)BQ*DIM_;

    float *qp, *offattn, *attnout, *xb, *yb, *ffn, *bcat;
    __half* valh;
    uint32_t* wp;
    cudaGetSymbolAddress((void**)&qp,      g_qp);
    cudaGetSymbolAddress((void**)&valh,    g_valh);
    cudaGetSymbolAddress((void**)&offattn, g_offattn);
    cudaGetSymbolAddress((void**)&attnout, g_attnout);
    cudaGetSymbolAddress((void**)&xb,      g_x);
    cudaGetSymbolAddress((void**)&yb,      g_y);
    cudaGetSymbolAddress((void**)&ffn,     g_ffn);
    cudaGetSymbolAddress((void**)&wp,      g_wp);
    cudaGetSymbolAddress((void**)&bcat,    g_bcat);

    // 0) pack all weights into fragment-direct layout + bias concat
    {
        WPackArgs a{Wv, Woff, Wattn, Wout, W1, W2, boff, battn};
        wconv_all<<<(376832 + 384 + 255)/256, 256>>>(a, wp, bcat);
    }

    // 1) qp = LN1(input) + pos
    ln_kernel<<<BQ, 256>>>(input, ln1_g, ln1_b, pos, qp);

    // 2) value = mask-zero(source @ Wv + bv) -> fp16
    gemm_bf<4><<<dim3(2, (MV + 63)/64), 128>>>(source, wp + WP_WV, bv, nullptr, mask,
                                               valh, MV, DIM_, DIM_, 0, 1);

    // 3) [offsets | attn logits] = qp @ [Woff|Wattn] + [boff|battn]
    gemm_bf<4><<<dim3(3, BQ/64), 128>>>(qp, wp + WP_PROJ, bcat, nullptr, nullptr,
                                        offattn, BQ, 384, DIM_, 0, 0);

    // 4) fused loc + softmax + deformable sampling
    sample_kernel<<<BQ, 128>>>(valh, offattn, refp, out_loc, attnout);

    // 5) x = input + attnout @ Wout + bout
    gemm_bf<4><<<dim3(2, BQ/64), 128>>>(attnout, wp + WP_WOUT, bout, input, nullptr,
                                        xb, BQ, DIM_, DIM_, 0, 0);

    // 6) y = LN2(x)
    ln_kernel<<<BQ, 256>>>(xb, ln2_g, ln2_b, nullptr, yb);

    // 7) ffn = relu(y @ W1 + b1)
    gemm_bf<4><<<dim3(DFF/128, BQ/64), 128>>>(yb, wp + WP_W1, b1, nullptr, nullptr,
                                              ffn, BQ, DFF, DIM_, 1, 0);

    // 8) out_x = x + ffn @ W2 + b2
    gemm_bf<4><<<dim3(2, BQ/64), 128>>>(ffn, wp + WP_W2, b2, xb, nullptr,
                                        out_x, BQ, DIM_, DFF, 0, 0);
}

// round 13
// speedup vs baseline: 1.1046x; 1.1046x over previous
#include <cuda_runtime.h>
#include <cuda_bf16.h>
#include <cuda_fp16.h>
#include <cstdint>

#define B_      8
#define Q_      2048
#define DIM_    256
#define NH      8
#define HD      32
#define DFF     1024
#define LEN_IN_ 13294
#define BQ      (B_*Q_)
#define MV      (B_*LEN_IN_)

// ---------------- scratch ----------------
__device__ float    g_qp[BQ*DIM_];
__device__ __half   g_valh[MV*DIM_];       // fp16 value (54 MB, L2-resident)
__device__ float    g_offattn[BQ*384];     // [off(256) | attn logits(128)]
__device__ float    g_attnout[BQ*DIM_];
__device__ float    g_x[BQ*DIM_];
__device__ float    g_y[BQ*DIM_];
__device__ float    g_ffn[BQ*DFF];
__device__ uint32_t g_wp[376832];          // packed bf16x2 weights (fragment layout)
__device__ float    g_bcat[384];           // concat bias [boff | battn]

// packed-weight word offsets
#define WP_WV    0
#define WP_PROJ  32768
#define WP_WOUT  81920
#define WP_W1    114688
#define WP_W2    245760

// ---------------- LayerNorm (+ optional additive term) ----------------
__global__ __launch_bounds__(256) void ln_kernel(
    const float* __restrict__ x, const float* __restrict__ g,
    const float* __restrict__ b, const float* __restrict__ addend,
    float* __restrict__ out)
{
    __shared__ float sbuf[8];
    const int row = blockIdx.x;
    const int t = threadIdx.x;
    const float v = x[(size_t)row*DIM_ + t];

    float s = v;
    #pragma unroll
    for (int o = 16; o; o >>= 1) s += __shfl_xor_sync(0xffffffffu, s, o);
    if ((t & 31) == 0) sbuf[t >> 5] = s;
    __syncthreads();
    float mean = 0.f;
    #pragma unroll
    for (int i = 0; i < 8; i++) mean += sbuf[i];
    mean *= (1.f/256.f);

    const float d = v - mean;
    float s2 = d*d;
    #pragma unroll
    for (int o = 16; o; o >>= 1) s2 += __shfl_xor_sync(0xffffffffu, s2, o);
    __syncthreads();
    if ((t & 31) == 0) sbuf[t >> 5] = s2;
    __syncthreads();
    float var = 0.f;
    #pragma unroll
    for (int i = 0; i < 8; i++) var += sbuf[i];
    var *= (1.f/256.f);

    float r = d * rsqrtf(var + 1e-5f) * g[t] + b[t];
    if (addend) r += addend[(size_t)row*DIM_ + t];
    out[(size_t)row*DIM_ + t] = r;
}

// ---------------- helpers ----------------
__device__ __forceinline__ uint32_t packbf(float lo, float hi) {
    uint32_t d;
    asm("cvt.rn.bf16x2.f32 %0, %1, %2;" : "=r"(d) : "f"(hi), "f"(lo));
    return d;
}

__device__ __forceinline__ void mma_bf16(float c[4], const uint32_t a[4],
                                         uint32_t b0, uint32_t b1) {
    asm("mma.sync.aligned.m16n8k16.row.col.f32.bf16.bf16.f32 "
        "{%0,%1,%2,%3}, {%4,%5,%6,%7}, {%8,%9}, {%0,%1,%2,%3};"
        : "+f"(c[0]), "+f"(c[1]), "+f"(c[2]), "+f"(c[3])
        : "r"(a[0]), "r"(a[1]), "r"(a[2]), "r"(a[3]), "r"(b0), "r"(b1));
}

// ---------------- single-launch weight pack (fragment-direct layout) ----------------
struct WPackArgs {
    const float *Wv, *Woff, *Wattn, *Wout, *W1, *W2, *boff, *battn;
};

__device__ __forceinline__ uint32_t frag_pack(const float* __restrict__ W,
                                              int N, int K32, int idx)
{
    const int blk  = idx >> 7;
    const int r    = idx & 127;
    const int lane = r >> 2;
    const int j    = r & 3;
    const int gid  = lane >> 2;
    const int tig  = lane & 3;
    const int n8   = blk / K32;
    const int t    = blk - n8 * K32;
    const int kp   = t*16 + tig + j*4;
    const int n    = n8*8 + gid;
    return packbf(W[(size_t)(2*kp)*N + n], W[(size_t)(2*kp+1)*N + n]);
}

__global__ __launch_bounds__(256) void wconv_all(WPackArgs a, uint32_t* __restrict__ out,
                                                 float* __restrict__ bcat)
{
    int idx = blockIdx.x * 256 + threadIdx.x;

    if (idx < 32768) { out[WP_WV + idx] = frag_pack(a.Wv, 256, 8, idx); return; }
    idx -= 32768;
    if (idx < 49152) {   // projcat K=256, N=384
        const int blk  = idx >> 7;
        const int r    = idx & 127;
        const int lane = r >> 2;
        const int j    = r & 3;
        const int gid  = lane >> 2;
        const int tig  = lane & 3;
        const int n8   = blk >> 3;
        const int t    = blk & 7;
        const int kp   = t*16 + tig + j*4;
        const int n    = n8*8 + gid;
        float lo, hi;
        if (n < 256) { lo = a.Woff[(size_t)(2*kp)*256 + n];      hi = a.Woff[(size_t)(2*kp+1)*256 + n]; }
        else         { lo = a.Wattn[(size_t)(2*kp)*128 + n-256]; hi = a.Wattn[(size_t)(2*kp+1)*128 + n-256]; }
        out[WP_PROJ + idx] = packbf(lo, hi);
        return;
    }
    idx -= 49152;
    if (idx < 32768) { out[WP_WOUT + idx] = frag_pack(a.Wout, 256, 8, idx); return; }
    idx -= 32768;
    if (idx < 131072) { out[WP_W1 + idx] = frag_pack(a.W1, 1024, 8, idx); return; }
    idx -= 131072;
    if (idx < 131072) { out[WP_W2 + idx] = frag_pack(a.W2, 256, 32, idx); return; }
    idx -= 131072;
    if (idx < 384) bcat[idx] = (idx < 256) ? a.boff[idx] : a.battn[idx - 256];
}

// ---------------- BF16 tensor-core GEMM (round-11 structure, 4 CTAs/SM) ----------------
// C = act(A @ W + bias) [+resid] [mask rows]; optional fp16 output.
// A fp32 [M,K]; Wp fragment layout. CTA: 128 threads, tile 64 x (WNT*32).
// A double-buffered in smem; B fragments register double-buffered.
#define A_STRB   80
#define A_STAGEB (64*A_STRB)

template<int WNT>
__global__ __launch_bounds__(128, 4) void gemm_bf(
    const float* __restrict__ A, const uint32_t* __restrict__ Wp,
    const float* __restrict__ bias, const float* __restrict__ resid,
    const uint8_t* __restrict__ mask, void* __restrict__ Cv,
    int M, int N, int K, int relu, int outhalf)
{
    __shared__ char smem[2*A_STAGEB];

    const int tid   = threadIdx.x;
    const int warpN = tid >> 5;
    const int lane  = tid & 31;
    const int gid   = lane >> 2;
    const int tig   = lane & 3;
    const int row0  = blockIdx.y * 64;
    const int col0  = blockIdx.x * (WNT*32);
    const int K32   = K >> 5;
    const int nblk0 = (col0 >> 3) + warpN*WNT;

    const int a_row  = tid >> 1;
    const int a_half = tid & 1;
    const bool avalid = (row0 + a_row) < M;
    const float* aptr = A + (size_t)(row0 + a_row) * K + a_half*16;

    const int lrow   = (lane & 7) + (((lane >> 3) & 1) << 3);
    const int lkhalf = (lane >> 4) & 1;
    const uint32_t a_sbase = (uint32_t)__cvta_generic_to_shared(smem);

    float acc[4][WNT][4];
    #pragma unroll
    for (int i = 0; i < 4; i++)
        #pragma unroll
        for (int j = 0; j < WNT; j++)
            #pragma unroll
            for (int r = 0; r < 4; r++) acc[i][j][r] = 0.f;

    float4 ra[4];
    auto stsA = [&](int p) {
        uint32_t w[8];
        #pragma unroll
        for (int i = 0; i < 4; i++) {
            w[i*2+0] = packbf(ra[i].x, ra[i].y);
            w[i*2+1] = packbf(ra[i].z, ra[i].w);
        }
        char* dst = smem + p*A_STAGEB + a_row*A_STRB + a_half*32;
        *(uint4*)(dst)      = make_uint4(w[0], w[1], w[2], w[3]);
        *(uint4*)(dst + 16) = make_uint4(w[4], w[5], w[6], w[7]);
    };

    uint4 bqb[2][WNT];

    // ---- prologue: A(0) + B(0), stage 0 ----
    #pragma unroll
    for (int i = 0; i < 4; i++)
        ra[i] = avalid ? *(const float4*)(aptr + i*4) : make_float4(0.f,0.f,0.f,0.f);
    #pragma unroll
    for (int nt = 0; nt < WNT; nt++)
        bqb[0][nt] = *(const uint4*)(Wp + (((size_t)(nblk0 + nt)*K32) << 7) + (lane << 2));
    stsA(0);

    #pragma unroll 2
    for (int t = 0; t < K32; t++) {
        const int p = t & 1;
        __syncthreads();

        const bool more = (t + 1) < K32;
        if (more) {
            const int k0n = (t + 1) << 5;
            #pragma unroll
            for (int i = 0; i < 4; i++)
                ra[i] = avalid ? *(const float4*)(aptr + k0n + i*4)
                               : make_float4(0.f,0.f,0.f,0.f);
            #pragma unroll
            for (int nt = 0; nt < WNT; nt++)
                bqb[p ^ 1][nt] = *(const uint4*)(Wp
                    + (((size_t)(nblk0 + nt)*K32 + t + 1) << 7) + (lane << 2));
        }

        // ---- all A fragments up front (8 LDSM), then MMA chain ----
        const uint32_t a_stage = a_sbase + (uint32_t)(p * A_STAGEB);
        uint32_t af[2][4][4];
        #pragma unroll
        for (int ks = 0; ks < 2; ks++)
            #pragma unroll
            for (int mt = 0; mt < 4; mt++) {
                const uint32_t addr = a_stage
                    + (uint32_t)((mt*16 + lrow)*A_STRB + ks*32 + lkhalf*16);
                asm volatile("ldmatrix.sync.aligned.m8n8.x4.shared.b16 {%0,%1,%2,%3}, [%4];"
                    : "=r"(af[ks][mt][0]), "=r"(af[ks][mt][1]),
                      "=r"(af[ks][mt][2]), "=r"(af[ks][mt][3]) : "r"(addr));
            }
        #pragma unroll
        for (int ks = 0; ks < 2; ks++)
            #pragma unroll
            for (int mt = 0; mt < 4; mt++)
                #pragma unroll
                for (int nt = 0; nt < WNT; nt++) {
                    if (ks == 0) mma_bf16(acc[mt][nt], af[0][mt], bqb[p][nt].x, bqb[p][nt].y);
                    else         mma_bf16(acc[mt][nt], af[1][mt], bqb[p][nt].z, bqb[p][nt].w);
                }

        if (more) stsA(p ^ 1);
    }

    // ---- epilogue ----
    #pragma unroll
    for (int mt = 0; mt < 4; mt++) {
        #pragma unroll
        for (int half = 0; half < 2; half++) {
            const int r = row0 + mt*16 + gid + half*8;
            if (r >= M) continue;
            const float mz = (mask && mask[r]) ? 0.f : 1.f;
            #pragma unroll
            for (int nt = 0; nt < WNT; nt++) {
                const int c = col0 + warpN*WNT*8 + nt*8 + 2*tig;
                float v0 = acc[mt][nt][half*2 + 0] + bias[c + 0];
                float v1 = acc[mt][nt][half*2 + 1] + bias[c + 1];
                if (relu) { v0 = fmaxf(v0, 0.f); v1 = fmaxf(v1, 0.f); }
                if (resid) {
                    const float* rp = resid + (size_t)r*N + c;
                    v0 += rp[0]; v1 += rp[1];
                }
                v0 *= mz; v1 *= mz;
                if (outhalf) {
                    __half2* hp = (__half2*)((__half*)Cv + (size_t)r*N + c);
                    *hp = __floats2half2_rn(v0, v1);
                } else {
                    *(float2*)((float*)Cv + (size_t)r*N + c) = make_float2(v0, v1);
                }
            }
        }
    }
}

// ---------------- fused loc + softmax + MS-deformable sampling (fp16 value) ----------------
__global__ __launch_bounds__(128) void sample_kernel(
    const __half* __restrict__ value, const float* __restrict__ offattn,
    const float* __restrict__ ref,
    float* __restrict__ out_loc, float* __restrict__ out)
{
    __shared__ float s_loc[256];
    __shared__ float s_attn[128];

    const int bq   = blockIdx.x;
    const int tid  = threadIdx.x;
    const int b    = bq >> 11;

    #pragma unroll
    for (int i = 0; i < 2; i++) {
        const int j = tid + i*128;
        const int c = j & 1;
        const int l = (j >> 3) & 3;
        const float nd[4] = {100.f, 50.f, 25.f, 13.f};
        const float v = ref[((size_t)bq*4 + l)*2 + c]
                      + offattn[(size_t)bq*384 + j] / nd[l];
        s_loc[j] = v;
        out_loc[(size_t)bq*256 + j] = v;
    }
    {
        const float logit = offattn[(size_t)bq*384 + 256 + tid];
        float m = logit;
        #pragma unroll
        for (int o = 8; o; o >>= 1) m = fmaxf(m, __shfl_xor_sync(0xffffffffu, m, o, 16));
        const float e = __expf(logit - m);
        float s = e;
        #pragma unroll
        for (int o = 8; o; o >>= 1) s += __shfl_xor_sync(0xffffffffu, s, o, 16);
        s_attn[tid] = e / s;
    }
    __syncthreads();

    const int warp = tid >> 5;
    const int lane = tid & 31;
    const int h    = warp*2 + (lane >> 4);
    const int cp   = lane & 15;

    const float* locp = s_loc  + h*32;
    const float* ap   = s_attn + h*16;

    constexpr int LH[4] = {100, 50, 25, 13};
    constexpr int LS[4] = {0, 10000, 12500, 13125};

    float a0 = 0.f, a1 = 0.f;
    #pragma unroll
    for (int l = 0; l < 4; l++) {
        const int Hh = LH[l], Ww = LH[l];
        const __half2* vb = (const __half2*)(value
            + ((size_t)b*LEN_IN_ + LS[l])*DIM_ + h*32) + cp;
        #pragma unroll
        for (int p = 0; p < 4; p++) {
            const float lx = locp[(l*4 + p)*2 + 0];
            const float ly = locp[(l*4 + p)*2 + 1];
            const float a  = ap[l*4 + p];
            const float x = lx * (float)Ww - 0.5f;
            const float y = ly * (float)Hh - 0.5f;
            const float x0f = floorf(x), y0f = floorf(y);
            const float wx = x - x0f, wy = y - y0f;
            const int x0 = (int)x0f, y0 = (int)y0f;
            const int x1 = x0 + 1,  y1 = y0 + 1;

            const float vx0 = (x0 >= 0 && x0 < Ww) ? 1.f : 0.f;
            const float vx1 = (x1 >= 0 && x1 < Ww) ? 1.f : 0.f;
            const float vy0 = (y0 >= 0 && y0 < Hh) ? 1.f : 0.f;
            const float vy1 = (y1 >= 0 && y1 < Hh) ? 1.f : 0.f;
            const int cx0 = min(max(x0, 0), Ww-1);
            const int cx1 = min(max(x1, 0), Ww-1);
            const int cy0 = min(max(y0, 0), Hh-1);
            const int cy1 = min(max(y1, 0), Hh-1);

            const float2 g00 = __half22float2(vb[(size_t)(cy0*Ww + cx0)*128]);
            const float2 g01 = __half22float2(vb[(size_t)(cy0*Ww + cx1)*128]);
            const float2 g10 = __half22float2(vb[(size_t)(cy1*Ww + cx0)*128]);
            const float2 g11 = __half22float2(vb[(size_t)(cy1*Ww + cx1)*128]);

            const float w00 = vx0*vy0*(1.f-wx)*(1.f-wy);
            const float w01 = vx1*vy0*wx*(1.f-wy);
            const float w10 = vx0*vy1*(1.f-wx)*wy;
            const float w11 = vx1*vy1*wx*wy;

            a0 += a * (g00.x*w00 + g01.x*w01 + g10.x*w10 + g11.x*w11);
            a1 += a * (g00.y*w00 + g01.y*w01 + g10.y*w10 + g11.y*w11);
        }
    }
    *(float2*)(out + (size_t)bq*256 + h*32 + cp*2) = make_float2(a0, a1);
}

// ---------------- launch ----------------
extern "C" void kernel_launch(void* const* d_in, const int* in_sizes, int n_in,
                              void* d_out, int out_size)
{
    const float*   input  = (const float*)d_in[0];
    const float*   pos    = (const float*)d_in[1];
    const float*   refp   = (const float*)d_in[2];
    const float*   source = (const float*)d_in[3];
    const uint8_t* mask   = (const uint8_t*)d_in[6];
    const float*   ln1_g  = (const float*)d_in[7];
    const float*   ln1_b  = (const float*)d_in[8];
    const float*   ln2_g  = (const float*)d_in[9];
    const float*   ln2_b  = (const float*)d_in[10];
    const float*   Wv     = (const float*)d_in[11];
    const float*   bv     = (const float*)d_in[12];
    const float*   Woff   = (const float*)d_in[13];
    const float*   boff   = (const float*)d_in[14];
    const float*   Wattn  = (const float*)d_in[15];
    const float*   battn  = (const float*)d_in[16];
    const float*   Wout   = (const float*)d_in[17];
    const float*   bout   = (const float*)d_in[18];
    const float*   W1     = (const float*)d_in[19];
    const float*   b1     = (const float*)d_in[20];
    const float*   W2     = (const float*)d_in[21];
    const float*   b2     = (const float*)d_in[22];

    float* out_x   = (float*)d_out;
    float* out_loc = (float*)d_out + (size_t)BQ*DIM_;

    float *qp, *offattn, *attnout, *xb, *yb, *ffn, *bcat;
    __half* valh;
    uint32_t* wp;
    cudaGetSymbolAddress((void**)&qp,      g_qp);
    cudaGetSymbolAddress((void**)&valh,    g_valh);
    cudaGetSymbolAddress((void**)&offattn, g_offattn);
    cudaGetSymbolAddress((void**)&attnout, g_attnout);
    cudaGetSymbolAddress((void**)&xb,      g_x);
    cudaGetSymbolAddress((void**)&yb,      g_y);
    cudaGetSymbolAddress((void**)&ffn,     g_ffn);
    cudaGetSymbolAddress((void**)&wp,      g_wp);
    cudaGetSymbolAddress((void**)&bcat,    g_bcat);

    // side stream + events for value-GEMM overlap (created once; host-side
    // objects only, no device allocation)
    static cudaStream_t s1 = nullptr;
    static cudaEvent_t  e0 = nullptr, e1 = nullptr;
    if (s1 == nullptr) {
        cudaStreamCreateWithFlags(&s1, cudaStreamNonBlocking);
        cudaEventCreateWithFlags(&e0, cudaEventDisableTiming);
        cudaEventCreateWithFlags(&e1, cudaEventDisableTiming);
    }

    // 0) pack all weights into fragment-direct layout + bias concat
    {
        WPackArgs a{Wv, Woff, Wattn, Wout, W1, W2, boff, battn};
        wconv_all<<<(376832 + 384 + 255)/256, 256>>>(a, wp, bcat);
    }

    // fork: value GEMM runs on s1 concurrently with LN1 + proj GEMM
    cudaEventRecord(e0, 0);
    cudaStreamWaitEvent(s1, e0, 0);

    // 2) value = mask-zero(source @ Wv + bv) -> fp16   [side stream]
    gemm_bf<4><<<dim3(2, (MV + 63)/64), 128, 0, s1>>>(source, wp + WP_WV, bv, nullptr, mask,
                                                      valh, MV, DIM_, DIM_, 0, 1);
    cudaEventRecord(e1, s1);

    // 1) qp = LN1(input) + pos                          [main stream]
    ln_kernel<<<BQ, 256>>>(input, ln1_g, ln1_b, pos, qp);

    // 3) [offsets | attn logits] = qp @ [Woff|Wattn] + [boff|battn]
    gemm_bf<4><<<dim3(3, BQ/64), 128>>>(qp, wp + WP_PROJ, bcat, nullptr, nullptr,
                                        offattn, BQ, 384, DIM_, 0, 0);

    // join: sampler needs both value and proj outputs
    cudaStreamWaitEvent(0, e1, 0);

    // 4) fused loc + softmax + deformable sampling
    sample_kernel<<<BQ, 128>>>(valh, offattn, refp, out_loc, attnout);

    // 5) x = input + attnout @ Wout + bout
    gemm_bf<4><<<dim3(2, BQ/64), 128>>>(attnout, wp + WP_WOUT, bout, input, nullptr,
                                        xb, BQ, DIM_, DIM_, 0, 0);

    // 6) y = LN2(x)
    ln_kernel<<<BQ, 256>>>(xb, ln2_g, ln2_b, nullptr, yb);

    // 7) ffn = relu(y @ W1 + b1)
    gemm_bf<4><<<dim3(DFF/128, BQ/64), 128>>>(yb, wp + WP_W1, b1, nullptr, nullptr,
                                              ffn, BQ, DFF, DIM_, 1, 0);

    // 8) out_x = x + ffn @ W2 + b2
    gemm_bf<4><<<dim3(2, BQ/64), 128>>>(ffn, wp + WP_W2, b2, xb, nullptr,
                                        out_x, BQ, DIM_, DFF, 0, 0);
}